// round 16
// baseline (speedup 1.0000x reference)
#include <cuda_runtime.h>
#include <cuda_fp16.h>
#include <cstdint>
#include <cstddef>

// Problem dims
#define NROWS 8192
#define KDIM  4096
#define ODIM  16384

// GEMM tiling: 128x128 CTA tile, 4 warps of 64x64, 2 CTAs/SM.
#define BM 128
#define BN 128
#define BK 64                 // 64 fp16 = 128 bytes per row (one SW128 atom row)
#define STAGES 3
#define NTHREADS 128
#define NCHUNK (KDIM / BK)    // 64

#define A_BYTES (BM * 128)            // 16384
#define B_BYTES (BN * 128)            // 16384
#define STAGE_BYTES (A_BYTES + B_BYTES)   // 32768
#define SMEM_BYTES (STAGE_BYTES * STAGES) // 98304 -> 2 CTAs = 196608

// fp16 scratch (device globals: no runtime allocation)
__device__ __half g_Wh[(size_t)ODIM * KDIM];   // 128 MiB
__device__ __half g_Xh[(size_t)NROWS * KDIM];  // 64 MiB
__device__ float  g_Bf[ODIM];

// ---------------- PTX helpers ----------------
__device__ __forceinline__ uint32_t smem_u32(const void* p) {
    uint32_t a;
    asm("{ .reg .u64 t; cvta.to.shared.u64 t, %1; cvt.u32.u64 %0, t; }" : "=r"(a) : "l"(p));
    return a;
}
__device__ __forceinline__ uint32_t sw128(uint32_t o) { return o ^ ((o >> 3) & 0x70); }

__device__ __forceinline__ void cp16(uint32_t s, const void* g) {
    asm volatile("cp.async.cg.shared.global [%0], [%1], 16;" :: "r"(s), "l"(g));
}

__device__ __forceinline__ void ldsm4(uint32_t* r, uint32_t addr) {
    asm volatile("ldmatrix.sync.aligned.m8n8.x4.shared.b16 {%0,%1,%2,%3}, [%4];"
                 : "=r"(r[0]), "=r"(r[1]), "=r"(r[2]), "=r"(r[3]) : "r"(addr));
}

__device__ __forceinline__ void mma16816(float* d, const uint32_t* a, const uint32_t* b) {
    asm volatile(
        "mma.sync.aligned.m16n8k16.row.col.f32.f16.f16.f32 "
        "{%0,%1,%2,%3}, {%4,%5,%6,%7}, {%8,%9}, {%0,%1,%2,%3};"
        : "+f"(d[0]), "+f"(d[1]), "+f"(d[2]), "+f"(d[3])
        : "r"(a[0]), "r"(a[1]), "r"(a[2]), "r"(a[3]), "r"(b[0]), "r"(b[1]));
}

// Streaming (evict-first) 64-bit global store: output is write-once.
__device__ __forceinline__ void stg64_cs(float* p, float x, float y) {
    asm volatile("st.global.cs.v2.f32 [%0], {%1, %2};" :: "l"(p), "f"(x), "f"(y) : "memory");
}

// Streaming float4 load / uint2 store for single-use conversion traffic.
__device__ __forceinline__ float4 ldg128_cs(const float4* p) {
    float4 v;
    asm volatile("ld.global.cs.v4.f32 {%0,%1,%2,%3}, [%4];"
                 : "=f"(v.x), "=f"(v.y), "=f"(v.z), "=f"(v.w) : "l"(p));
    return v;
}
__device__ __forceinline__ void stg64u_cs(uint2* p, uint2 v) {
    asm volatile("st.global.cs.v2.u32 [%0], {%1, %2};" :: "l"(p), "r"(v.x), "r"(v.y) : "memory");
}

// ---------------- fused elementwise conversion (one launch, streaming) ----------------
#define WQUADS ((size_t)ODIM * KDIM / 4)   // 16.78M float4
#define XQUADS ((size_t)NROWS * KDIM / 4)  // 8.39M float4

__global__ void convert_all_kernel(const float4* __restrict__ wmu,
                                   const float4* __restrict__ wls,
                                   const float4* __restrict__ wep,
                                   const float4* __restrict__ x,
                                   const float* __restrict__ bmu,
                                   const float* __restrict__ bls,
                                   const float* __restrict__ eb) {
    const size_t total = WQUADS + XQUADS;
    uint2* w4 = reinterpret_cast<uint2*>(g_Wh);
    uint2* x4 = reinterpret_cast<uint2*>(g_Xh);
    size_t idx = (size_t)blockIdx.x * blockDim.x + threadIdx.x;
    // Bias handled by the first 16384 threads (cheap, once).
    if (idx < ODIM) g_Bf[idx] = fmaf(__expf(bls[idx]), eb[idx], bmu[idx]);
    for (size_t i = idx; i < total; i += (size_t)gridDim.x * blockDim.x) {
        if (i < WQUADS) {
            float4 m = ldg128_cs(wmu + i);
            float4 l = ldg128_cs(wls + i);
            float4 e = ldg128_cs(wep + i);
            float a0 = fmaf(__expf(l.x), e.x, m.x);
            float a1 = fmaf(__expf(l.y), e.y, m.y);
            float a2 = fmaf(__expf(l.z), e.z, m.z);
            float a3 = fmaf(__expf(l.w), e.w, m.w);
            __half2 h0 = __floats2half2_rn(a0, a1);
            __half2 h1 = __floats2half2_rn(a2, a3);
            uint2 u;
            u.x = *reinterpret_cast<uint32_t*>(&h0);
            u.y = *reinterpret_cast<uint32_t*>(&h1);
            stg64u_cs(w4 + i, u);
        } else {
            size_t j = i - WQUADS;
            float4 v = ldg128_cs(x + j);
            __half2 h0 = __floats2half2_rn(v.x, v.y);
            __half2 h1 = __floats2half2_rn(v.z, v.w);
            uint2 u;
            u.x = *reinterpret_cast<uint32_t*>(&h0);
            u.y = *reinterpret_cast<uint32_t*>(&h1);
            stg64u_cs(x4 + j, u);
        }
    }
}

// ---------------- GEMM (R15: protected, byte-identical) ----------------
__global__ void __launch_bounds__(NTHREADS, 2) gemm_kernel(float* __restrict__ out) {
    extern __shared__ char smem[];
    const uint32_t smem_base = smem_u32(smem);
    const int tid = threadIdx.x;
    const int wid = tid >> 5;
    const int lane = tid & 31;

    // Supertile rasterization: 8 M-tiles per band, sweep N; A panels stay in L2.
    const int TN = ODIM / BN;   // 128
    const int SUPER = 8;
    int bid = blockIdx.x;
    int band = bid / (SUPER * TN);
    int r = bid % (SUPER * TN);
    int mb = band * SUPER + (r % SUPER);
    int nb = r / SUPER;
    const int m_base = mb * BM;
    const int n_base = nb * BN;

    // Warp tile: 64x64. 4 warps: warp_m = wid&1 (2), warp_n = wid>>1 (2).
    const int wm = (wid & 1) * 64;
    const int wn = (wid >> 1) * 64;

    const char* Abase = (const char*)(g_Xh) + (size_t)m_base * KDIM * 2;
    const char* Bbase = (const char*)(g_Wh) + (size_t)n_base * KDIM * 2;

    // ---- ldmatrix per-lane addressing (swizzle-correct) ----
    // sw128(row*128 + col) == row*128 + (col ^ ((row&7)<<4)) for col<128.
    const int a_tile = lane >> 3;
    const int a_row = (lane & 7) + ((a_tile & 1) << 3);
    const int a_kc = a_tile >> 1;
    const uint32_t a_rowoff = (uint32_t)(wm + a_row) * 128;
    const uint32_t a_mask = (uint32_t)(a_row & 7) << 4;
    const uint32_t a_colbase = (uint32_t)(a_kc * 16);
    const int b_row = (lane & 7) + ((lane >> 4) << 3);
    const int b_kc = (lane >> 3) & 1;
    const uint32_t b_rowoff = (uint32_t)(wn + b_row) * 128;
    const uint32_t b_mask = (uint32_t)(b_row & 7) << 4;
    const uint32_t b_colbase = (uint32_t)(b_kc * 16);

    float acc[4][8][4];
#pragma unroll
    for (int mi = 0; mi < 4; mi++)
#pragma unroll
        for (int ni = 0; ni < 8; ni++)
#pragma unroll
            for (int q = 0; q < 4; q++) acc[mi][ni][q] = 0.0f;

    // Prologue: fully load chunks 0 and 1.
#pragma unroll
    for (int s = 0; s < 2; s++) {
        uint32_t sa = smem_base + s * STAGE_BYTES;
        uint32_t sb = sa + A_BYTES;
        const char* Ag = Abase + (size_t)s * BK * 2;
        const char* Bg = Bbase + (size_t)s * BK * 2;
#pragma unroll
        for (int j = 0; j < 8; j++) {
            int g = j * NTHREADS + tid;
            int row = g >> 3, c = g & 7;
            cp16(sa + sw128((uint32_t)(row * 128 + c * 16)),
                 Ag + (size_t)row * (KDIM * 2) + c * 16);
        }
#pragma unroll
        for (int j = 0; j < 8; j++) {
            int g = j * NTHREADS + tid;
            int row = g >> 3, c = g & 7;
            cp16(sb + sw128((uint32_t)(row * 128 + c * 16)),
                 Bg + (size_t)row * (KDIM * 2) + c * 16);
        }
        asm volatile("cp.async.commit_group;" ::: "memory");
    }

    for (int i = 0; i < NCHUNK; i++) {
        // Chunk i's loads are the oldest outstanding group; allow 1 pending (i+1).
        asm volatile("cp.async.wait_group %0;" :: "n"(1));
        __syncthreads();

        uint32_t sa = smem_base + (i % STAGES) * STAGE_BYTES;
        uint32_t sb = sa + A_BYTES;
        const uint32_t abase = sa + a_rowoff;
        const uint32_t bbase = sb + b_rowoff;

        // Next-next chunk load setup (issued interleaved, 4 cp16 per ks step).
        const int lc = i + 2;
        const bool do_load = lc < NCHUNK;
        uint32_t la = smem_base + (lc % STAGES) * STAGE_BYTES;
        uint32_t lb = la + A_BYTES;
        const char* Ag = Abase + (size_t)lc * BK * 2;
        const char* Bg = Bbase + (size_t)lc * BK * 2;

#pragma unroll
        for (int ks = 0; ks < BK / 16; ks++) {
            const uint32_t acol = (a_colbase + (uint32_t)(ks * 32)) ^ a_mask;
            const uint32_t bcol = (b_colbase + (uint32_t)(ks * 32)) ^ b_mask;
            uint32_t afr[4][4], bfr[4][4];
#pragma unroll
            for (int mi = 0; mi < 4; mi++)
                ldsm4(afr[mi], abase + (uint32_t)(mi * 2048) + acol);
#pragma unroll
            for (int nb4 = 0; nb4 < 4; nb4++)
                ldsm4(bfr[nb4], bbase + (uint32_t)(nb4 * 2048) + bcol);

            // De-burst: 4 cp.async here fill the ldsm->mma dependency latency.
            if (do_load) {
#pragma unroll
                for (int j = 2 * ks; j < 2 * ks + 2; j++) {
                    int g = j * NTHREADS + tid;
                    int row = g >> 3, c = g & 7;
                    cp16(la + sw128((uint32_t)(row * 128 + c * 16)),
                         Ag + (size_t)row * (KDIM * 2) + c * 16);
                }
#pragma unroll
                for (int j = 2 * ks; j < 2 * ks + 2; j++) {
                    int g = j * NTHREADS + tid;
                    int row = g >> 3, c = g & 7;
                    cp16(lb + sw128((uint32_t)(row * 128 + c * 16)),
                         Bg + (size_t)row * (KDIM * 2) + c * 16);
                }
            }

#pragma unroll
            for (int mi = 0; mi < 4; mi++)
#pragma unroll
                for (int ni = 0; ni < 8; ni++)
                    mma16816(acc[mi][ni], afr[mi], &bfr[ni >> 1][(ni & 1) * 2]);
        }
        asm volatile("cp.async.commit_group;" ::: "memory");
    }

    // Epilogue: hoisted bias (8 distinct float2 per thread, reused across mi),
    // streaming stores (write-once output; don't evict L2 operand panels).
    {
        float2 bv[8];
#pragma unroll
        for (int ni = 0; ni < 8; ni++)
            bv[ni] = *reinterpret_cast<const float2*>(
                g_Bf + n_base + wn + ni * 8 + (lane & 3) * 2);
#pragma unroll
        for (int mi = 0; mi < 4; mi++) {
            int r0 = m_base + wm + mi * 16 + (lane >> 2);
            float* row0 = out + (size_t)r0 * ODIM;
            float* row1 = row0 + (size_t)8 * ODIM;
#pragma unroll
            for (int ni = 0; ni < 8; ni++) {
                int c = n_base + wn + ni * 8 + (lane & 3) * 2;
                stg64_cs(row0 + c, acc[mi][ni][0] + bv[ni].x, acc[mi][ni][1] + bv[ni].y);
                stg64_cs(row1 + c, acc[mi][ni][2] + bv[ni].x, acc[mi][ni][3] + bv[ni].y);
            }
        }
    }
}

// ---------------- launch ----------------
extern "C" void kernel_launch(void* const* d_in, const int* in_sizes, int n_in,
                              void* d_out, int out_size) {
    const float* x   = (const float*)d_in[0];
    const float* wmu = (const float*)d_in[1];
    const float* wls = (const float*)d_in[2];
    const float* bmu = (const float*)d_in[3];
    const float* bls = (const float*)d_in[4];
    const float* ew  = (const float*)d_in[5];
    const float* eb  = (const float*)d_in[6];
    float* out = (float*)d_out;

    convert_all_kernel<<<12288, 256>>>((const float4*)wmu, (const float4*)wls,
                                       (const float4*)ew, (const float4*)x,
                                       bmu, bls, eb);

    cudaFuncSetAttribute(gemm_kernel, cudaFuncAttributeMaxDynamicSharedMemorySize, SMEM_BYTES);
    const int grid = (NROWS / BM) * (ODIM / BN);   // 8192
    gemm_kernel<<<grid, NTHREADS, SMEM_BYTES>>>(out);
}

// round 17
// speedup vs baseline: 1.0026x; 1.0026x over previous
#include <cuda_runtime.h>
#include <cuda_fp16.h>
#include <cstdint>
#include <cstddef>

// Problem dims
#define NROWS 8192
#define KDIM  4096
#define ODIM  16384

// GEMM tiling: 128x128 CTA tile, 4 warps of 64x64, 2 CTAs/SM.
#define BM 128
#define BN 128
#define BK 64                 // 64 fp16 = 128 bytes per row (one SW128 atom row)
#define STAGES 3
#define NTHREADS 128
#define NCHUNK (KDIM / BK)    // 64

#define A_BYTES (BM * 128)            // 16384
#define B_BYTES (BN * 128)            // 16384
#define STAGE_BYTES (A_BYTES + B_BYTES)   // 32768
#define SMEM_BYTES (STAGE_BYTES * STAGES) // 98304 -> 2 CTAs = 196608

// fp16 scratch (device globals: no runtime allocation)
__device__ __half g_Wh[(size_t)ODIM * KDIM];   // 128 MiB
__device__ __half g_Xh[(size_t)NROWS * KDIM];  // 64 MiB
__device__ float  g_Bf[ODIM];

// ---------------- PTX helpers ----------------
__device__ __forceinline__ uint32_t smem_u32(const void* p) {
    uint32_t a;
    asm("{ .reg .u64 t; cvta.to.shared.u64 t, %1; cvt.u32.u64 %0, t; }" : "=r"(a) : "l"(p));
    return a;
}
__device__ __forceinline__ uint32_t sw128(uint32_t o) { return o ^ ((o >> 3) & 0x70); }

__device__ __forceinline__ void cp16(uint32_t s, const void* g) {
    asm volatile("cp.async.cg.shared.global [%0], [%1], 16;" :: "r"(s), "l"(g));
}

__device__ __forceinline__ void ldsm4(uint32_t* r, uint32_t addr) {
    asm volatile("ldmatrix.sync.aligned.m8n8.x4.shared.b16 {%0,%1,%2,%3}, [%4];"
                 : "=r"(r[0]), "=r"(r[1]), "=r"(r[2]), "=r"(r[3]) : "r"(addr));
}

__device__ __forceinline__ void mma16816(float* d, const uint32_t* a, const uint32_t* b) {
    asm volatile(
        "mma.sync.aligned.m16n8k16.row.col.f32.f16.f16.f32 "
        "{%0,%1,%2,%3}, {%4,%5,%6,%7}, {%8,%9}, {%0,%1,%2,%3};"
        : "+f"(d[0]), "+f"(d[1]), "+f"(d[2]), "+f"(d[3])
        : "r"(a[0]), "r"(a[1]), "r"(a[2]), "r"(a[3]), "r"(b[0]), "r"(b[1]));
}

// Streaming (evict-first) 64-bit global store: output is write-once.
__device__ __forceinline__ void stg64_cs(float* p, float x, float y) {
    asm volatile("st.global.cs.v2.f32 [%0], {%1, %2};" :: "l"(p), "f"(x), "f"(y) : "memory");
}

// ---------------- fused elementwise conversion (one launch) ----------------
// Static block partitioning: blocks [0, WBLOCKS) handle W (16.78M quads),
// blocks [WBLOCKS, WBLOCKS+XBLOCKS) handle X (8.39M quads). Each sub-grid's
// stride loop is branch-free (exactly 8 iterations per thread).
#define WQUADS ((size_t)ODIM * KDIM / 4)   // 16.78M float4
#define XQUADS ((size_t)NROWS * KDIM / 4)  // 8.39M float4
#define CVT_THREADS 256
#define WBLOCKS 8192                        // 8192*256*8 = 16.78M
#define XBLOCKS 4096                        // 4096*256*8 = 8.39M

__global__ void convert_all_kernel(const float4* __restrict__ wmu,
                                   const float4* __restrict__ wls,
                                   const float4* __restrict__ wep,
                                   const float4* __restrict__ x,
                                   const float* __restrict__ bmu,
                                   const float* __restrict__ bls,
                                   const float* __restrict__ eb) {
    uint2* w4 = reinterpret_cast<uint2*>(g_Wh);
    uint2* x4 = reinterpret_cast<uint2*>(g_Xh);
    const int b = blockIdx.x;
    size_t idx = (size_t)b * CVT_THREADS + threadIdx.x;
    // Bias handled by the first 16384 threads (cheap, once).
    if (idx < ODIM) g_Bf[idx] = fmaf(__expf(bls[idx]), eb[idx], bmu[idx]);

    if (b < WBLOCKS) {
        const size_t stride = (size_t)WBLOCKS * CVT_THREADS;
#pragma unroll 2
        for (size_t i = idx; i < WQUADS; i += stride) {
            float4 m = wmu[i], l = wls[i], e = wep[i];
            float a0 = fmaf(__expf(l.x), e.x, m.x);
            float a1 = fmaf(__expf(l.y), e.y, m.y);
            float a2 = fmaf(__expf(l.z), e.z, m.z);
            float a3 = fmaf(__expf(l.w), e.w, m.w);
            __half2 h0 = __floats2half2_rn(a0, a1);
            __half2 h1 = __floats2half2_rn(a2, a3);
            uint2 u;
            u.x = *reinterpret_cast<uint32_t*>(&h0);
            u.y = *reinterpret_cast<uint32_t*>(&h1);
            w4[i] = u;
        }
    } else {
        const size_t stride = (size_t)XBLOCKS * CVT_THREADS;
        size_t j = (size_t)(b - WBLOCKS) * CVT_THREADS + threadIdx.x;
#pragma unroll 2
        for (; j < XQUADS; j += stride) {
            float4 v = x[j];
            __half2 h0 = __floats2half2_rn(v.x, v.y);
            __half2 h1 = __floats2half2_rn(v.z, v.w);
            uint2 u;
            u.x = *reinterpret_cast<uint32_t*>(&h0);
            u.y = *reinterpret_cast<uint32_t*>(&h1);
            x4[j] = u;
        }
    }
}

// ---------------- GEMM (R15: measured best, byte-identical) ----------------
__global__ void __launch_bounds__(NTHREADS, 2) gemm_kernel(float* __restrict__ out) {
    extern __shared__ char smem[];
    const uint32_t smem_base = smem_u32(smem);
    const int tid = threadIdx.x;
    const int wid = tid >> 5;
    const int lane = tid & 31;

    // Supertile rasterization: 8 M-tiles per band, sweep N; A panels stay in L2.
    const int TN = ODIM / BN;   // 128
    const int SUPER = 8;
    int bid = blockIdx.x;
    int band = bid / (SUPER * TN);
    int r = bid % (SUPER * TN);
    int mb = band * SUPER + (r % SUPER);
    int nb = r / SUPER;
    const int m_base = mb * BM;
    const int n_base = nb * BN;

    // Warp tile: 64x64. 4 warps: warp_m = wid&1 (2), warp_n = wid>>1 (2).
    const int wm = (wid & 1) * 64;
    const int wn = (wid >> 1) * 64;

    const char* Abase = (const char*)(g_Xh) + (size_t)m_base * KDIM * 2;
    const char* Bbase = (const char*)(g_Wh) + (size_t)n_base * KDIM * 2;

    // ---- ldmatrix per-lane addressing (swizzle-correct) ----
    // sw128(row*128 + col) == row*128 + (col ^ ((row&7)<<4)) for col<128.
    const int a_tile = lane >> 3;
    const int a_row = (lane & 7) + ((a_tile & 1) << 3);
    const int a_kc = a_tile >> 1;
    const uint32_t a_rowoff = (uint32_t)(wm + a_row) * 128;
    const uint32_t a_mask = (uint32_t)(a_row & 7) << 4;
    const uint32_t a_colbase = (uint32_t)(a_kc * 16);
    const int b_row = (lane & 7) + ((lane >> 4) << 3);
    const int b_kc = (lane >> 3) & 1;
    const uint32_t b_rowoff = (uint32_t)(wn + b_row) * 128;
    const uint32_t b_mask = (uint32_t)(b_row & 7) << 4;
    const uint32_t b_colbase = (uint32_t)(b_kc * 16);

    float acc[4][8][4];
#pragma unroll
    for (int mi = 0; mi < 4; mi++)
#pragma unroll
        for (int ni = 0; ni < 8; ni++)
#pragma unroll
            for (int q = 0; q < 4; q++) acc[mi][ni][q] = 0.0f;

    // Prologue: fully load chunks 0 and 1.
#pragma unroll
    for (int s = 0; s < 2; s++) {
        uint32_t sa = smem_base + s * STAGE_BYTES;
        uint32_t sb = sa + A_BYTES;
        const char* Ag = Abase + (size_t)s * BK * 2;
        const char* Bg = Bbase + (size_t)s * BK * 2;
#pragma unroll
        for (int j = 0; j < 8; j++) {
            int g = j * NTHREADS + tid;
            int row = g >> 3, c = g & 7;
            cp16(sa + sw128((uint32_t)(row * 128 + c * 16)),
                 Ag + (size_t)row * (KDIM * 2) + c * 16);
        }
#pragma unroll
        for (int j = 0; j < 8; j++) {
            int g = j * NTHREADS + tid;
            int row = g >> 3, c = g & 7;
            cp16(sb + sw128((uint32_t)(row * 128 + c * 16)),
                 Bg + (size_t)row * (KDIM * 2) + c * 16);
        }
        asm volatile("cp.async.commit_group;" ::: "memory");
    }

    for (int i = 0; i < NCHUNK; i++) {
        // Chunk i's loads are the oldest outstanding group; allow 1 pending (i+1).
        asm volatile("cp.async.wait_group %0;" :: "n"(1));
        __syncthreads();

        uint32_t sa = smem_base + (i % STAGES) * STAGE_BYTES;
        uint32_t sb = sa + A_BYTES;
        const uint32_t abase = sa + a_rowoff;
        const uint32_t bbase = sb + b_rowoff;

        // Next-next chunk load setup (issued interleaved, 4 cp16 per ks step).
        const int lc = i + 2;
        const bool do_load = lc < NCHUNK;
        uint32_t la = smem_base + (lc % STAGES) * STAGE_BYTES;
        uint32_t lb = la + A_BYTES;
        const char* Ag = Abase + (size_t)lc * BK * 2;
        const char* Bg = Bbase + (size_t)lc * BK * 2;

#pragma unroll
        for (int ks = 0; ks < BK / 16; ks++) {
            const uint32_t acol = (a_colbase + (uint32_t)(ks * 32)) ^ a_mask;
            const uint32_t bcol = (b_colbase + (uint32_t)(ks * 32)) ^ b_mask;
            uint32_t afr[4][4], bfr[4][4];
#pragma unroll
            for (int mi = 0; mi < 4; mi++)
                ldsm4(afr[mi], abase + (uint32_t)(mi * 2048) + acol);
#pragma unroll
            for (int nb4 = 0; nb4 < 4; nb4++)
                ldsm4(bfr[nb4], bbase + (uint32_t)(nb4 * 2048) + bcol);

            // De-burst: 4 cp.async here fill the ldsm->mma dependency latency.
            if (do_load) {
#pragma unroll
                for (int j = 2 * ks; j < 2 * ks + 2; j++) {
                    int g = j * NTHREADS + tid;
                    int row = g >> 3, c = g & 7;
                    cp16(la + sw128((uint32_t)(row * 128 + c * 16)),
                         Ag + (size_t)row * (KDIM * 2) + c * 16);
                }
#pragma unroll
                for (int j = 2 * ks; j < 2 * ks + 2; j++) {
                    int g = j * NTHREADS + tid;
                    int row = g >> 3, c = g & 7;
                    cp16(lb + sw128((uint32_t)(row * 128 + c * 16)),
                         Bg + (size_t)row * (KDIM * 2) + c * 16);
                }
            }

#pragma unroll
            for (int mi = 0; mi < 4; mi++)
#pragma unroll
                for (int ni = 0; ni < 8; ni++)
                    mma16816(acc[mi][ni], afr[mi], &bfr[ni >> 1][(ni & 1) * 2]);
        }
        asm volatile("cp.async.commit_group;" ::: "memory");
    }

    // Epilogue: hoisted bias (8 distinct float2 per thread, reused across mi),
    // streaming stores (write-once output; don't evict L2 operand panels).
    {
        float2 bv[8];
#pragma unroll
        for (int ni = 0; ni < 8; ni++)
            bv[ni] = *reinterpret_cast<const float2*>(
                g_Bf + n_base + wn + ni * 8 + (lane & 3) * 2);
#pragma unroll
        for (int mi = 0; mi < 4; mi++) {
            int r0 = m_base + wm + mi * 16 + (lane >> 2);
            float* row0 = out + (size_t)r0 * ODIM;
            float* row1 = row0 + (size_t)8 * ODIM;
#pragma unroll
            for (int ni = 0; ni < 8; ni++) {
                int c = n_base + wn + ni * 8 + (lane & 3) * 2;
                stg64_cs(row0 + c, acc[mi][ni][0] + bv[ni].x, acc[mi][ni][1] + bv[ni].y);
                stg64_cs(row1 + c, acc[mi][ni][2] + bv[ni].x, acc[mi][ni][3] + bv[ni].y);
            }
        }
    }
}

// ---------------- launch ----------------
extern "C" void kernel_launch(void* const* d_in, const int* in_sizes, int n_in,
                              void* d_out, int out_size) {
    const float* x   = (const float*)d_in[0];
    const float* wmu = (const float*)d_in[1];
    const float* wls = (const float*)d_in[2];
    const float* bmu = (const float*)d_in[3];
    const float* bls = (const float*)d_in[4];
    const float* ew  = (const float*)d_in[5];
    const float* eb  = (const float*)d_in[6];
    float* out = (float*)d_out;

    convert_all_kernel<<<WBLOCKS + XBLOCKS, CVT_THREADS>>>(
        (const float4*)wmu, (const float4*)wls, (const float4*)ew,
        (const float4*)x, bmu, bls, eb);

    cudaFuncSetAttribute(gemm_kernel, cudaFuncAttributeMaxDynamicSharedMemorySize, SMEM_BYTES);
    const int grid = (NROWS / BM) * (ODIM / BN);   // 8192
    gemm_kernel<<<grid, NTHREADS, SMEM_BYTES>>>(out);
}